// round 9
// baseline (speedup 1.0000x reference)
#include <cuda_runtime.h>

// ---------------------------------------------------------------------------
// CausalTrajectoryPrediction: 64 per-node MLPs, B=1024, H=512, M=64, N=64.
//   h1 = relu(x_masked @ W1^T); r1 = relu(h1 @ W2^T)
//   h3 = relu(r1 @ W3[:, :64]^T + x_own * W3[:, 64+n] + b3)
//   out = relu(h3 @ W4 + b4)
// One CTA per (node n, 128-row batch tile), fully fused in SMEM, fp32 with
// packed fma.rn.f32x2 (Blackwell). This revision: conflict-free B LDS.128,
// k-vectorized A loads, prefetch + double-buffered weight tiles.
// ---------------------------------------------------------------------------

#define THREADS 256
#define LDA 68   // padded row stride (floats), 16B aligned, bank-skewed

typedef unsigned long long ull;

__device__ __forceinline__ ull pk2(float lo, float hi) {
    ull r; asm("mov.b64 %0, {%1, %2};" : "=l"(r) : "f"(lo), "f"(hi)); return r;
}
__device__ __forceinline__ float2 upk2(ull v) {
    float2 r; asm("mov.b64 {%0, %1}, %2;" : "=f"(r.x), "=f"(r.y) : "l"(v)); return r;
}
__device__ __forceinline__ void fma2(ull& d, ull a, ull b) {
    asm("fma.rn.f32x2 %0, %1, %2, %0;" : "+l"(d) : "l"(a), "l"(b));
}

// ---- 64x64 weight tile staging ---------------------------------------------
// Physical layout: element (k, c) -> W[k*64 + 4*(((c>>2) ^ (k>>2)) & 15) + (c&3)]
// src: 64 rows (one per output col c), contiguous along k: src[c*rowstride + k].

__device__ __forceinline__ void ldg_tile(float4 w[4], const float* __restrict__ src,
                                         int rowstride) {
    int f  = threadIdx.x & 15;
    int c0 = threadIdx.x >> 4;
#pragma unroll
    for (int p = 0; p < 4; ++p)
        w[p] = *(const float4*)(src + (size_t)(c0 + 16 * p) * rowstride + f * 4);
}

__device__ __forceinline__ void sts_tile(float* __restrict__ W, const float4 w[4]) {
    int f  = threadIdx.x & 15;
    int c0 = threadIdx.x >> 4;
#pragma unroll
    for (int p = 0; p < 4; ++p) {
        int c = c0 + 16 * p;
        int g = ((c >> 2) ^ f) & 15;
        int base = f * 256 + (g << 2) + (c & 3);
        W[base      ] = w[p].x;   // k = 4f
        W[base +  64] = w[p].y;   // k = 4f+1
        W[base + 128] = w[p].z;   // k = 4f+2
        W[base + 192] = w[p].w;   // k = 4f+3
    }
}

// ---- 128x64x64 GEMM microkernel --------------------------------------------
// Thread (rt, ct): rows {rt+32i}, cols {4ct..4ct+3} U {32+4ct..32+4ct+3}.
// acc[i][0..1] = col pairs (4ct,4ct+1),(4ct+2,4ct+3); acc[i][2..3] = +32.
__device__ __forceinline__ void gemm64(ull acc[4][4],
                                       const float* __restrict__ A,
                                       const float* __restrict__ W,
                                       int rt, int ct) {
    const float* Ab = A + rt * LDA;
#pragma unroll 4
    for (int k4 = 0; k4 < 64; k4 += 4) {
        float4 av[4];
#pragma unroll
        for (int i = 0; i < 4; ++i)
            av[i] = *(const float4*)(Ab + i * (32 * LDA) + k4);
        int s  = k4 >> 2;
        int g0 = (((ct    ) ^ s) & 15) << 2;
        int g1 = (((ct + 8) ^ s) & 15) << 2;
#pragma unroll
        for (int j = 0; j < 4; ++j) {
            const float* Wk = W + (k4 + j) * 64;
            ulonglong2 b01 = *(const ulonglong2*)(Wk + g0);
            ulonglong2 b23 = *(const ulonglong2*)(Wk + g1);
            float aj[4] = {av[0].x, av[0].y, av[0].z, av[0].w};
            // index j of av[i] without dynamic indexing:
            float a0 = (j == 0) ? av[0].x : (j == 1) ? av[0].y : (j == 2) ? av[0].z : av[0].w;
            float a1 = (j == 0) ? av[1].x : (j == 1) ? av[1].y : (j == 2) ? av[1].z : av[1].w;
            float a2 = (j == 0) ? av[2].x : (j == 1) ? av[2].y : (j == 2) ? av[2].z : av[2].w;
            float a3 = (j == 0) ? av[3].x : (j == 1) ? av[3].y : (j == 2) ? av[3].z : av[3].w;
            (void)aj;
            ull p0 = pk2(a0, a0), p1 = pk2(a1, a1), p2 = pk2(a2, a2), p3 = pk2(a3, a3);
            fma2(acc[0][0], p0, b01.x); fma2(acc[0][1], p0, b01.y);
            fma2(acc[0][2], p0, b23.x); fma2(acc[0][3], p0, b23.y);
            fma2(acc[1][0], p1, b01.x); fma2(acc[1][1], p1, b01.y);
            fma2(acc[1][2], p1, b23.x); fma2(acc[1][3], p1, b23.y);
            fma2(acc[2][0], p2, b01.x); fma2(acc[2][1], p2, b01.y);
            fma2(acc[2][2], p2, b23.x); fma2(acc[2][3], p2, b23.y);
            fma2(acc[3][0], p3, b01.x); fma2(acc[3][1], p3, b01.y);
            fma2(acc[3][2], p3, b23.x); fma2(acc[3][3], p3, b23.y);
        }
    }
}

__global__ void __launch_bounds__(THREADS, 2)
ctp_kernel(const float* __restrict__ x,  const float* __restrict__ W1,
           const float* __restrict__ W2, const float* __restrict__ W3,
           const float* __restrict__ b3, const float* __restrict__ W4,
           const float* __restrict__ b4, float* __restrict__ out) {
    extern __shared__ float sm[];
    float* Asm = sm;                 // 128 x 68 = 8704 (x tile, later r1)
    float* Hsm = Asm + 8704;         // 128 x 68 = 8704 (h1 chunk)
    float* Wa  = Hsm + 8704;         // 4096 (swizzled weight tile A)
    float* Wb  = Wa  + 4096;         // 4096 (swizzled weight tile B)
    float* W4s = Wb  + 4096;         // 512
    float* w3o = W4s + 512;          // 2 x 64 (own-input col, double buffer)
    float* b3s = w3o + 128;          // 2 x 64 (bias chunk, double buffer)
    float* xow = b3s + 128;          // 128 (x[:, n])

    const int n       = blockIdx.y;
    const int rowbase = blockIdx.x * 128;
    const int tid     = threadIdx.x;
    const int rt      = tid >> 3;    // 0..31 -> rows rt, rt+32, rt+64, rt+96
    const int ct      = tid & 7;     // 0..7  -> cols 4ct..4ct+3 and +32

    const float* W1n = W1 + (size_t)n * 512 * 64;
    const float* W2n = W2 + (size_t)n * 64 * 512;
    const float* W3n = W3 + (size_t)n * 512 * 128;

    // ---- Stage x tile (col n masked), W4, x_own; prefetch W1[0], W2[0] ----
    {
        int f  = tid & 15;
        int r0 = tid >> 4;
#pragma unroll
        for (int p = 0; p < 8; ++p) {
            int row = r0 + p * 16;
            float4 v = *(const float4*)(x + (size_t)(rowbase + row) * 64 + f * 4);
            v.x = (4 * f + 0 == n) ? 0.0f : v.x;
            v.y = (4 * f + 1 == n) ? 0.0f : v.y;
            v.z = (4 * f + 2 == n) ? 0.0f : v.z;
            v.w = (4 * f + 3 == n) ? 0.0f : v.w;
            *(float4*)(Asm + row * LDA + f * 4) = v;
        }
    }
    for (int i = tid; i < 512; i += THREADS) W4s[i] = W4[(size_t)n * 512 + i];
    if (tid < 128) xow[tid] = x[(size_t)(rowbase + tid) * 64 + n];

    float4 w[4];
    ldg_tile(w, W1n, 64);            // W1 chunk 0
    sts_tile(Wa, w);
    ldg_tile(w, W2n, 512);           // W2 chunk 0 (held in regs)
    __syncthreads();                 // Asm, Wa, W4s, xow visible

    // ---- Phase B: r1 = relu( relu(A @ W1^T) @ W2^T ), chunked over H ------
    ull r1acc[4][4];
#pragma unroll
    for (int i = 0; i < 4; ++i)
#pragma unroll
        for (int q = 0; q < 4; ++q) r1acc[i][q] = 0ull;

    for (int hc = 0; hc < 8; ++hc) {
        ull acc[4][4];
#pragma unroll
        for (int i = 0; i < 4; ++i)
#pragma unroll
            for (int q = 0; q < 4; ++q) acc[i][q] = 0ull;
        gemm64(acc, Asm, Wa, rt, ct);        // h1 chunk = x @ W1[hc]^T

        __syncthreads();   // gemm1 done by all (Wa free); gemm2(hc-1) done (Hsm/Wb free)

        // relu(h1) -> Hsm as two float4 stores; stage W2[hc] into Wb;
        // prefetch next W1 (or W3[0] at the tail).
#pragma unroll
        for (int i = 0; i < 4; ++i) {
            int row = rt + 32 * i;
            float2 v0 = upk2(acc[i][0]), v1 = upk2(acc[i][1]);
            float2 v2 = upk2(acc[i][2]), v3 = upk2(acc[i][3]);
            float4 lo = {fmaxf(v0.x, 0.f), fmaxf(v0.y, 0.f), fmaxf(v1.x, 0.f), fmaxf(v1.y, 0.f)};
            float4 hi = {fmaxf(v2.x, 0.f), fmaxf(v2.y, 0.f), fmaxf(v3.x, 0.f), fmaxf(v3.y, 0.f)};
            *(float4*)(Hsm + row * LDA + 4 * ct)      = lo;
            *(float4*)(Hsm + row * LDA + 32 + 4 * ct) = hi;
        }
        sts_tile(Wb, w);                                   // W2[hc]
        if (hc < 7) ldg_tile(w, W1n + (size_t)(hc + 1) * 4096, 64);
        else        ldg_tile(w, W3n, 128);                 // W3 chunk 0
        __syncthreads();   // Hsm, Wb ready

        gemm64(r1acc, Hsm, Wb, rt, ct);      // r1 += h1 @ W2[hc]^T

        if (hc < 7) {
            sts_tile(Wa, w);                               // W1[hc+1]
            ldg_tile(w, W2n + (size_t)(hc + 1) * 64, 512); // W2[hc+1]
            __syncthreads();   // Wa ready for next gemm1
        }
    }

    // ---- r1 = relu(r1acc) overlaid into Asm; stage W3[0], aux[0] ----------
#pragma unroll
    for (int i = 0; i < 4; ++i) {
        int row = rt + 32 * i;
        float2 v0 = upk2(r1acc[i][0]), v1 = upk2(r1acc[i][1]);
        float2 v2 = upk2(r1acc[i][2]), v3 = upk2(r1acc[i][3]);
        float4 lo = {fmaxf(v0.x, 0.f), fmaxf(v0.y, 0.f), fmaxf(v1.x, 0.f), fmaxf(v1.y, 0.f)};
        float4 hi = {fmaxf(v2.x, 0.f), fmaxf(v2.y, 0.f), fmaxf(v3.x, 0.f), fmaxf(v3.y, 0.f)};
        *(float4*)(Asm + row * LDA + 4 * ct)      = lo;
        *(float4*)(Asm + row * LDA + 32 + 4 * ct) = hi;
    }
    sts_tile(Wa, w);                          // W3[0] (w loaded at hc==7 above)
    ldg_tile(w, W3n + 8192, 128);             // W3[1]
    if (tid < 64) {
        w3o[tid] = W3n[(size_t)tid * 128 + 64 + n];
        b3s[tid] = b3[(size_t)n * 512 + tid];
    }
    __syncthreads();   // Asm(r1), Wa(W3[0]), aux[0] ready

    // ---- Phase C: out = relu( relu(R @ W3a^T + x_own*w3own + b3) @ W4 + b4 )
    float partial[4] = {0.f, 0.f, 0.f, 0.f};
    const float b4n = b4[n];
    const int clo = 4 * ct, chi = 32 + 4 * ct;
    float xo[4];
#pragma unroll
    for (int i = 0; i < 4; ++i) xo[i] = xow[rt + 32 * i];

    for (int hc = 0; hc < 8; ++hc) {
        int buf = hc & 1;
        const float* Wc = buf ? Wb : Wa;
        const float* wo = w3o + buf * 64;
        const float* bb = b3s + buf * 64;

        ull acc[4][4];
#pragma unroll
        for (int i = 0; i < 4; ++i) {
            acc[i][0] = pk2(fmaf(xo[i], wo[clo],     bb[clo]),
                            fmaf(xo[i], wo[clo + 1], bb[clo + 1]));
            acc[i][1] = pk2(fmaf(xo[i], wo[clo + 2], bb[clo + 2]),
                            fmaf(xo[i], wo[clo + 3], bb[clo + 3]));
            acc[i][2] = pk2(fmaf(xo[i], wo[chi],     bb[chi]),
                            fmaf(xo[i], wo[chi + 1], bb[chi + 1]));
            acc[i][3] = pk2(fmaf(xo[i], wo[chi + 2], bb[chi + 2]),
                            fmaf(xo[i], wo[chi + 3], bb[chi + 3]));
        }
        gemm64(acc, Asm, Wc, rt, ct);

        // relu(h3 chunk) folded into the W4 dot product
#pragma unroll
        for (int i = 0; i < 4; ++i) {
#pragma unroll
            for (int q = 0; q < 4; ++q) {
                float2 v = upk2(acc[i][q]);
                int c = hc * 64 + ((q < 2) ? (clo + 2 * q) : (chi + 2 * (q - 2)));
                partial[i] = fmaf(fmaxf(v.x, 0.f), W4s[c],     partial[i]);
                partial[i] = fmaf(fmaxf(v.y, 0.f), W4s[c + 1], partial[i]);
            }
        }

        if (hc < 7) {
            __syncthreads();   // all threads done gemm3(hc); other buffer free
            float* Wn = buf ? Wa : Wb;
            sts_tile(Wn, w);                    // W3[hc+1]
            if (tid < 64) {
                int h = (hc + 1) * 64 + tid;
                w3o[(1 - buf) * 64 + tid] = W3n[(size_t)h * 128 + 64 + n];
                b3s[(1 - buf) * 64 + tid] = b3[(size_t)n * 512 + h];
            }
            if (hc + 2 < 8) ldg_tile(w, W3n + (size_t)(hc + 2) * 8192, 128);
            __syncthreads();   // next buffer ready
        }
    }

    // ---- Reduce over the 8 ct lanes (lanes differ in tid bits 0..2) -------
#pragma unroll
    for (int i = 0; i < 4; ++i) {
        float v = partial[i];
        v += __shfl_xor_sync(0xffffffffu, v, 1);
        v += __shfl_xor_sync(0xffffffffu, v, 2);
        v += __shfl_xor_sync(0xffffffffu, v, 4);
        if (ct == 0)
            out[(size_t)(rowbase + rt + 32 * i) * 64 + n] = fmaxf(v + b4n, 0.0f);
    }
}

extern "C" void kernel_launch(void* const* d_in, const int* in_sizes, int n_in,
                              void* d_out, int out_size) {
    const float* x  = (const float*)d_in[0];
    const float* W1 = (const float*)d_in[1];
    const float* W2 = (const float*)d_in[2];
    const float* W3 = (const float*)d_in[3];
    const float* b3 = (const float*)d_in[4];
    const float* W4 = (const float*)d_in[5];
    const float* b4 = (const float*)d_in[6];
    float* out = (float*)d_out;

    const int smem_bytes = 26496 * (int)sizeof(float);  // 105984 B, 2 CTAs/SM
    cudaFuncSetAttribute(ctp_kernel,
                         cudaFuncAttributeMaxDynamicSharedMemorySize,
                         smem_bytes);

    dim3 grid(8, 64);   // 8 row tiles of 128 x 64 nodes
    ctp_kernel<<<grid, THREADS, smem_bytes>>>(x, W1, W2, W3, b3, W4, b4, out);
}

// round 11
// speedup vs baseline: 1.7895x; 1.7895x over previous
#include <cuda_runtime.h>

// ---------------------------------------------------------------------------
// CausalTrajectoryPrediction: 64 per-node MLPs, B=1024, H=512, M=64, N=64.
//   h1 = relu(x_masked @ W1^T); r1 = relu(h1 @ W2^T)
//   h3 = relu(r1 @ W3[:, :64]^T + x_own * W3[:, 64+n] + b3)
//   out = relu(h3 @ W4 + b4)
// One CTA per (node n, 128-row batch tile), fully fused in SMEM, fp32 with
// packed fma.rn.f32x2. This revision: 128 threads x (8 rows x 8 cols) register
// tile (halves LDS.128 per FMA vs R9), and minimal-sync pipelined staging.
// ---------------------------------------------------------------------------

#define THREADS 128
#define LDA 68   // padded row stride (floats), 16B aligned, bank-skewed

typedef unsigned long long ull;

__device__ __forceinline__ ull pk2(float lo, float hi) {
    ull r; asm("mov.b64 %0, {%1, %2};" : "=l"(r) : "f"(lo), "f"(hi)); return r;
}
__device__ __forceinline__ float2 upk2(ull v) {
    float2 r; asm("mov.b64 {%0, %1}, %2;" : "=f"(r.x), "=f"(r.y) : "l"(v)); return r;
}
__device__ __forceinline__ void fma2(ull& d, ull a, ull b) {
    asm("fma.rn.f32x2 %0, %1, %2, %0;" : "+l"(d) : "l"(a), "l"(b));
}

// ---- 64x64 weight tile staging ---------------------------------------------
// Physical layout: element (k, c) -> W[k*64 + 4*(((c>>2) ^ (k>>2)) & 15) + (c&3)]
// src: 64 rows (one per output col c), contiguous along k: src[c*rowstride + k].

__device__ __forceinline__ void ldg_tile(float4 w[8], const float* __restrict__ src,
                                         int rowstride) {
    int f  = threadIdx.x & 15;
    int c0 = threadIdx.x >> 4;   // 0..7
#pragma unroll
    for (int p = 0; p < 8; ++p)
        w[p] = *(const float4*)(src + (size_t)(c0 + 8 * p) * rowstride + f * 4);
}

__device__ __forceinline__ void sts_tile(float* __restrict__ W, const float4 w[8]) {
    int f  = threadIdx.x & 15;
    int c0 = threadIdx.x >> 4;
#pragma unroll
    for (int p = 0; p < 8; ++p) {
        int c = c0 + 8 * p;
        int g = ((c >> 2) ^ f) & 15;
        int base = f * 256 + (g << 2) + (c & 3);
        W[base      ] = w[p].x;   // k = 4f
        W[base +  64] = w[p].y;   // k = 4f+1
        W[base + 128] = w[p].z;   // k = 4f+2
        W[base + 192] = w[p].w;   // k = 4f+3
    }
}

// ---- 128x64x64 GEMM microkernel --------------------------------------------
// Thread (rt, ct): rows {rt + 16i, i=0..7}, cols {4ct..4ct+3} U {32+4ct..+3}.
// acc[i][0..1] = col pairs (4ct,4ct+1),(4ct+2,4ct+3); acc[i][2..3] = +32.
__device__ __forceinline__ void gemm64(ull acc[8][4],
                                       const float* __restrict__ A,
                                       const float* __restrict__ W,
                                       int rt, int ct) {
    const float* Ab = A + rt * LDA;
#pragma unroll 4
    for (int k4 = 0; k4 < 64; k4 += 4) {
        float4 av[8];
#pragma unroll
        for (int i = 0; i < 8; ++i)
            av[i] = *(const float4*)(Ab + i * (16 * LDA) + k4);
        int s  = k4 >> 2;
        int g0 = (((ct    ) ^ s) & 15) << 2;
        int g1 = (((ct + 8) ^ s) & 15) << 2;
#pragma unroll
        for (int j = 0; j < 4; ++j) {
            const float* Wk = W + (k4 + j) * 64;
            ulonglong2 b01 = *(const ulonglong2*)(Wk + g0);
            ulonglong2 b23 = *(const ulonglong2*)(Wk + g1);
#pragma unroll
            for (int i = 0; i < 8; ++i) {
                float a = (j == 0) ? av[i].x : (j == 1) ? av[i].y
                         : (j == 2) ? av[i].z : av[i].w;
                ull p = pk2(a, a);
                fma2(acc[i][0], p, b01.x);
                fma2(acc[i][1], p, b01.y);
                fma2(acc[i][2], p, b23.x);
                fma2(acc[i][3], p, b23.y);
            }
        }
    }
}

__global__ void __launch_bounds__(THREADS, 2)
ctp_kernel(const float* __restrict__ x,  const float* __restrict__ W1,
           const float* __restrict__ W2, const float* __restrict__ W3,
           const float* __restrict__ b3, const float* __restrict__ W4,
           const float* __restrict__ b4, float* __restrict__ out) {
    extern __shared__ float sm[];
    float* Asm = sm;                 // 128 x 68 = 8704 (x tile, later r1)
    float* Hsm = Asm + 8704;         // 128 x 68 = 8704 (h1 chunk)
    float* Wa  = Hsm + 8704;         // 4096 (swizzled weight tile A)
    float* Wb  = Wa  + 4096;         // 4096 (swizzled weight tile B)
    float* W4s = Wb  + 4096;         // 512
    float* w3o = W4s + 512;          // 2 x 64 (own-input col, double buffer)
    float* b3s = w3o + 128;          // 2 x 64 (bias chunk, double buffer)
    float* xow = b3s + 128;          // 128 (x[:, n])

    const int n       = blockIdx.y;
    const int rowbase = blockIdx.x * 128;
    const int tid     = threadIdx.x;
    const int rt      = tid >> 3;    // 0..15 -> rows rt + 16i
    const int ct      = tid & 7;     // 0..7  -> cols 4ct..4ct+3 and +32

    const float* W1n = W1 + (size_t)n * 512 * 64;
    const float* W2n = W2 + (size_t)n * 64 * 512;
    const float* W3n = W3 + (size_t)n * 512 * 128;

    // ---- Stage x tile (col n masked), W4, x_own; prefetch W1[0], W2[0] ----
    {
        int f  = tid & 15;
        int r0 = tid >> 4;           // 0..7
#pragma unroll
        for (int p = 0; p < 16; ++p) {
            int row = r0 + p * 8;
            float4 v = *(const float4*)(x + (size_t)(rowbase + row) * 64 + f * 4);
            v.x = (4 * f + 0 == n) ? 0.0f : v.x;
            v.y = (4 * f + 1 == n) ? 0.0f : v.y;
            v.z = (4 * f + 2 == n) ? 0.0f : v.z;
            v.w = (4 * f + 3 == n) ? 0.0f : v.w;
            *(float4*)(Asm + row * LDA + f * 4) = v;
        }
    }
    for (int i = tid; i < 512; i += THREADS) W4s[i] = W4[(size_t)n * 512 + i];
    xow[tid] = x[(size_t)(rowbase + tid) * 64 + n];

    float4 w[8];
    ldg_tile(w, W1n, 64);            // W1 chunk 0
    sts_tile(Wa, w);
    ldg_tile(w, W2n, 512);           // W2 chunk 0 (held in regs)
    __syncthreads();                 // Asm, Wa, W4s, xow visible

    // ---- Phase B: r1 = relu( relu(A @ W1^T) @ W2^T ), 2 syncs per chunk ---
    ull r1acc[8][4];
#pragma unroll
    for (int i = 0; i < 8; ++i)
#pragma unroll
        for (int q = 0; q < 4; ++q) r1acc[i][q] = 0ull;

    for (int hc = 0; hc < 8; ++hc) {
        ull acc[8][4];
#pragma unroll
        for (int i = 0; i < 8; ++i)
#pragma unroll
            for (int q = 0; q < 4; ++q) acc[i][q] = 0ull;
        gemm64(acc, Asm, Wa, rt, ct);        // h1 chunk = x @ W1[hc]^T

        // relu(h1) -> Hsm (own region; gemm2(hc-1) finished at prev sync2).
        // Stage W2[hc] into Wb (free since prev sync2). Prefetch next W1/W3.
#pragma unroll
        for (int i = 0; i < 8; ++i) {
            int row = rt + 16 * i;
            float2 v0 = upk2(acc[i][0]), v1 = upk2(acc[i][1]);
            float2 v2 = upk2(acc[i][2]), v3 = upk2(acc[i][3]);
            float4 lo = {fmaxf(v0.x, 0.f), fmaxf(v0.y, 0.f), fmaxf(v1.x, 0.f), fmaxf(v1.y, 0.f)};
            float4 hi = {fmaxf(v2.x, 0.f), fmaxf(v2.y, 0.f), fmaxf(v3.x, 0.f), fmaxf(v3.y, 0.f)};
            *(float4*)(Hsm + row * LDA + 4 * ct)      = lo;
            *(float4*)(Hsm + row * LDA + 32 + 4 * ct) = hi;
        }
        sts_tile(Wb, w);                                   // W2[hc]
        if (hc < 7) ldg_tile(w, W1n + (size_t)(hc + 1) * 4096, 64);
        else        ldg_tile(w, W3n, 128);                 // W3 chunk 0
        __syncthreads();   // sync1: Hsm + Wb visible; gemm1 done (Wa free)

        gemm64(r1acc, Hsm, Wb, rt, ct);      // r1 += h1 @ W2[hc]^T

        if (hc < 7) {
            sts_tile(Wa, w);                               // W1[hc+1] (Wa free)
            ldg_tile(w, W2n + (size_t)(hc + 1) * 64, 512); // W2[hc+1]
            __syncthreads();   // sync2: Wa visible; gemm2 done (Hsm/Wb free)
        }
    }

    // ---- r1 = relu(r1acc) -> Asm (free: gemm1(7) done at last sync1) ------
#pragma unroll
    for (int i = 0; i < 8; ++i) {
        int row = rt + 16 * i;
        float2 v0 = upk2(r1acc[i][0]), v1 = upk2(r1acc[i][1]);
        float2 v2 = upk2(r1acc[i][2]), v3 = upk2(r1acc[i][3]);
        float4 lo = {fmaxf(v0.x, 0.f), fmaxf(v0.y, 0.f), fmaxf(v1.x, 0.f), fmaxf(v1.y, 0.f)};
        float4 hi = {fmaxf(v2.x, 0.f), fmaxf(v2.y, 0.f), fmaxf(v3.x, 0.f), fmaxf(v3.y, 0.f)};
        *(float4*)(Asm + row * LDA + 4 * ct)      = lo;
        *(float4*)(Asm + row * LDA + 32 + 4 * ct) = hi;
    }
    sts_tile(Wa, w);                          // W3[0]  (w set at hc==7 above)
    ldg_tile(w, W3n + 8192, 128);             // W3[1]
    if (tid < 64) {
        w3o[tid] = W3n[(size_t)tid * 128 + 64 + n];
        b3s[tid] = b3[(size_t)n * 512 + tid];
    }
    __syncthreads();   // Asm(r1), Wa(W3[0]), aux[0] visible; gemm2(7) done

    // ---- Phase C: out = relu( relu(R @ W3a^T + x_own*w3own + b3) @ W4 + b4 )
    float partial[8] = {0.f, 0.f, 0.f, 0.f, 0.f, 0.f, 0.f, 0.f};
    const float b4n = b4[n];
    const int clo = 4 * ct, chi = 32 + 4 * ct;
    float xo[8];
#pragma unroll
    for (int i = 0; i < 8; ++i) xo[i] = xow[rt + 16 * i];

    for (int hc = 0; hc < 8; ++hc) {
        int buf = hc & 1;
        const float* Wc = buf ? Wb : Wa;
        const float* wo = w3o + buf * 64;
        const float* bb = b3s + buf * 64;

        ull acc[8][4];
#pragma unroll
        for (int i = 0; i < 8; ++i) {
            acc[i][0] = pk2(fmaf(xo[i], wo[clo],     bb[clo]),
                            fmaf(xo[i], wo[clo + 1], bb[clo + 1]));
            acc[i][1] = pk2(fmaf(xo[i], wo[clo + 2], bb[clo + 2]),
                            fmaf(xo[i], wo[clo + 3], bb[clo + 3]));
            acc[i][2] = pk2(fmaf(xo[i], wo[chi],     bb[chi]),
                            fmaf(xo[i], wo[chi + 1], bb[chi + 1]));
            acc[i][3] = pk2(fmaf(xo[i], wo[chi + 2], bb[chi + 2]),
                            fmaf(xo[i], wo[chi + 3], bb[chi + 3]));
        }
        gemm64(acc, Asm, Wc, rt, ct);

        // relu(h3 chunk) folded into the W4 dot product
#pragma unroll
        for (int i = 0; i < 8; ++i) {
#pragma unroll
            for (int q = 0; q < 4; ++q) {
                float2 v = upk2(acc[i][q]);
                int c = hc * 64 + ((q < 2) ? (clo + 2 * q) : (chi + 2 * (q - 2)));
                partial[i] = fmaf(fmaxf(v.x, 0.f), W4s[c],     partial[i]);
                partial[i] = fmaf(fmaxf(v.y, 0.f), W4s[c + 1], partial[i]);
            }
        }

        if (hc < 7) {
            // Stage next buffer while others finish gemm3(hc): the buffer
            // being overwritten was last read by gemm3(hc-1), which completed
            // at the previous bottom sync.
            float* Wn = buf ? Wa : Wb;
            sts_tile(Wn, w);                    // W3[hc+1]
            if (tid < 64) {
                int h = (hc + 1) * 64 + tid;
                w3o[(1 - buf) * 64 + tid] = W3n[(size_t)h * 128 + 64 + n];
                b3s[(1 - buf) * 64 + tid] = b3[(size_t)n * 512 + h];
            }
            if (hc + 2 < 8) ldg_tile(w, W3n + (size_t)(hc + 2) * 8192, 128);
            __syncthreads();   // next buffer ready; gemm3(hc) done everywhere
        }
    }

    // ---- Reduce over the 8 ct lanes (lanes differ in tid bits 0..2) -------
#pragma unroll
    for (int i = 0; i < 8; ++i) {
        float v = partial[i];
        v += __shfl_xor_sync(0xffffffffu, v, 1);
        v += __shfl_xor_sync(0xffffffffu, v, 2);
        v += __shfl_xor_sync(0xffffffffu, v, 4);
        if (ct == 0)
            out[(size_t)(rowbase + rt + 16 * i) * 64 + n] = fmaxf(v + b4n, 0.0f);
    }
}

extern "C" void kernel_launch(void* const* d_in, const int* in_sizes, int n_in,
                              void* d_out, int out_size) {
    const float* x  = (const float*)d_in[0];
    const float* W1 = (const float*)d_in[1];
    const float* W2 = (const float*)d_in[2];
    const float* W3 = (const float*)d_in[3];
    const float* b3 = (const float*)d_in[4];
    const float* W4 = (const float*)d_in[5];
    const float* b4 = (const float*)d_in[6];
    float* out = (float*)d_out;

    const int smem_bytes = 26496 * (int)sizeof(float);  // 105984 B, 2 CTAs/SM
    cudaFuncSetAttribute(ctp_kernel,
                         cudaFuncAttributeMaxDynamicSharedMemorySize,
                         smem_bytes);

    dim3 grid(8, 64);   // 8 row tiles of 128 x 64 nodes
    ctp_kernel<<<grid, THREADS, smem_bytes>>>(x, W1, W2, W3, b3, W4, b4, out);
}